// round 2
// baseline (speedup 1.0000x reference)
#include <cuda_runtime.h>
#include <math.h>

#define EMBED 384
#define NHEADS 12
#define NPOINTS 9
#define NLAYERS 2
#define KFG 20
#define KBG 50
#define KTOT 70
#define NITER 10
#define BB 4
#define HH 64
#define WW 64
#define NN (HH*WW)
#define BNTOT (BB*NN)
#define FFN 1152

// ---------------- scratch (device globals; allocation-free) ----------------
__device__ float g_x[BNTOT*EMBED];
__device__ float g_pos[BNTOT*EMBED];
__device__ float g_tmp[BNTOT*EMBED];
__device__ float g_v[BNTOT*EMBED];
__device__ float g_attn[BNTOT*EMBED];
__device__ float g_off[BNTOT*NHEADS*NPOINTS*2];
__device__ float g_aw[BNTOT*NHEADS*NPOINTS];
__device__ float g_hid[BNTOT*FFN];
__device__ float g_notpad[BNTOT];
__device__ float g_wfg[BNTOT];
__device__ float g_wbg[BNTOT];
__device__ float g_xsq[BNTOT];
__device__ float g_xemb[BNTOT];
__device__ float g_yemb[BNTOT];
__device__ int   g_list[BB*2*NN];
__device__ int   g_cnt[BB*2];
__device__ float g_cent[BB*KTOT*EMBED];
__device__ float g_num[BB*KTOT*EMBED];
__device__ float g_den[BB*KTOT];
__device__ float g_csq[BB*KTOT];

// ---------------- prep ----------------
__global__ void k_masks(const float* __restrict__ pad, const float* __restrict__ supp) {
    int i = blockIdx.x * blockDim.x + threadIdx.x;
    if (i < BNTOT) {
        float np = (pad[i] == 255.0f) ? 0.f : 1.f;
        float ob = (supp[i] == 1.0f) ? 1.f : 0.f;
        g_notpad[i] = np;
        g_wfg[i] = ob * np;
        g_wbg[i] = (1.f - ob) * np;
    }
    if (i < BB*KTOT*EMBED) g_num[i] = 0.f;
    if (i < BB*KTOT) g_den[i] = 0.f;
}

__global__ void k_transpose(const float* __restrict__ sx) {
    __shared__ float tile[32][33];
    int b = blockIdx.z;
    int n0 = blockIdx.x * 32, c0 = blockIdx.y * 32;
    for (int r = threadIdx.y; r < 32; r += 8)
        tile[r][threadIdx.x] = sx[((size_t)b*EMBED + c0 + r)*NN + n0 + threadIdx.x];
    __syncthreads();
    for (int r = threadIdx.y; r < 32; r += 8)
        g_x[((size_t)b*NN + n0 + r)*EMBED + c0 + threadIdx.x] = tile[threadIdx.x][r];
}

__global__ void k_xsq() {
    int row = blockIdx.x;
    const float* xr = g_x + (size_t)row*EMBED;
    int tid = threadIdx.x;
    float s = 0.f;
    for (int c = tid; c < EMBED; c += 128) { float v = xr[c]; s += v*v; }
    __shared__ float red[128];
    red[tid] = s; __syncthreads();
    for (int o = 64; o; o >>= 1) { if (tid < o) red[tid] += red[tid+o]; __syncthreads(); }
    if (tid == 0) g_xsq[row] = red[0];
}

__global__ void k_cumx() {
    int t = blockIdx.x * blockDim.x + threadIdx.x;
    if (t >= BB*HH) return;
    int b = t / HH, i = t % HH;
    const float* np_ = g_notpad + (b*NN + i*WW);
    float tot = 0.f;
    for (int j = 0; j < WW; j++) tot += np_[j];
    float last = tot + 1e-6f;
    float cum = 0.f;
    const float sc = 6.283185307179586f;
    for (int j = 0; j < WW; j++) {
        cum += np_[j];
        g_xemb[b*NN + i*WW + j] = cum / last * sc;
    }
}

__global__ void k_cumy() {
    int t = blockIdx.x * blockDim.x + threadIdx.x;
    if (t >= BB*WW) return;
    int b = t / WW, j = t % WW;
    const float* np_ = g_notpad + b*NN + j;
    float tot = 0.f;
    for (int i = 0; i < HH; i++) tot += np_[i*WW];
    float last = tot + 1e-6f;
    float cum = 0.f;
    const float sc = 6.283185307179586f;
    for (int i = 0; i < HH; i++) {
        cum += np_[i*WW];
        g_yemb[b*NN + i*WW + j] = cum / last * sc;
    }
}

__global__ void k_pos() {
    int idx = blockIdx.x;          // b*NN + n
    int c = threadIdx.x;           // 0..383
    float emb; int cc;
    if (c < 192) { emb = g_yemb[idx]; cc = c; }
    else         { emb = g_xemb[idx]; cc = c - 192; }
    float e = (float)(2*(cc/2)) / 192.f;
    // 1/dim_t = 10000^{-e} = 2^{-e*log2(10000)}
    float inv = exp2f(-e * 13.287712379549449f);
    float s = emb * inv;
    float v = (cc & 1) ? cosf(s) : sinf(s);
    g_pos[(size_t)idx*EMBED + c] = v;
}

// ---------------- k-means ----------------
__global__ void k_compact() {
    int b = blockIdx.x >> 1, grp = blockIdx.x & 1;
    const float* w = (grp == 0 ? g_wfg : g_wbg) + b*NN;
    int* list = g_list + (b*2 + grp)*NN;
    __shared__ int sscan[256];
    __shared__ int sbase;
    int tid = threadIdx.x;
    if (tid == 0) sbase = 0;
    __syncthreads();
    // pass 1: w > 0 (in-group), index ascending; pass 2: w == 0 fallback
    for (int pass = 0; pass < 2; pass++) {
        for (int c0 = 0; c0 < NN; c0 += 256) {
            int n = c0 + tid;
            int f = (pass == 0) ? (w[n] > 0.f ? 1 : 0) : (w[n] > 0.f ? 0 : 1);
            sscan[tid] = f; __syncthreads();
            for (int o = 1; o < 256; o <<= 1) {
                int v = (tid >= o) ? sscan[tid-o] : 0;
                __syncthreads();
                sscan[tid] += v;
                __syncthreads();
            }
            int mybase = sbase;
            if (f) list[mybase + sscan[tid] - 1] = n;
            __syncthreads();
            if (tid == 255) sbase = mybase + sscan[255];
            __syncthreads();
        }
        if (pass == 0 && tid == 0) g_cnt[b*2 + grp] = sbase;
        __syncthreads();
    }
    // init centers = first K list entries
    int K = (grp == 0) ? KFG : KBG;
    float* cent = g_cent + (size_t)(b*KTOT + (grp ? KFG : 0))*EMBED;
    for (int t = tid; t < K*EMBED; t += 256) {
        int k = t / EMBED, c = t % EMBED;
        cent[(size_t)k*EMBED + c] = g_x[((size_t)b*NN + list[k])*EMBED + c];
    }
}

__global__ void k_csq() {
    int r = blockIdx.x;
    int tid = threadIdx.x;
    const float* cr = g_cent + (size_t)r*EMBED;
    float s = 0.f;
    for (int c = tid; c < EMBED; c += 128) { float v = cr[c]; s += v*v; }
    __shared__ float red[128];
    red[tid] = s; __syncthreads();
    for (int o = 64; o; o >>= 1) { if (tid < o) red[tid] += red[tid+o]; __syncthreads(); }
    if (tid == 0) g_csq[r] = red[0];
}

__global__ void k_assign() {
    int bg = blockIdx.y;
    int b = bg >> 1, grp = bg & 1;
    int warp = threadIdx.x >> 5, lane = threadIdx.x & 31;
    int pi = blockIdx.x * (blockDim.x >> 5) + warp;
    int cnt = g_cnt[bg];
    if (pi >= cnt) return;
    int n = g_list[bg*NN + pi];
    int K = grp ? KBG : KFG;
    int rbase = b*KTOT + (grp ? KFG : 0);
    const float* xr = g_x + ((size_t)b*NN + n)*EMBED;
    float xv[12];
    #pragma unroll
    for (int t = 0; t < 12; t++) xv[t] = xr[lane + t*32];
    float xsq = g_xsq[b*NN + n];
    float dmin = INFINITY; int kmin = 0;
    for (int k = 0; k < K; k++) {
        const float* cr = g_cent + (size_t)(rbase + k)*EMBED;
        float p = 0.f;
        #pragma unroll
        for (int t = 0; t < 12; t++) p += xv[t]*cr[lane + t*32];
        #pragma unroll
        for (int o = 16; o; o >>= 1) p += __shfl_xor_sync(0xFFFFFFFFu, p, o);
        float d = (xsq - 2.f*p) + g_csq[rbase + k];
        if (d < dmin) { dmin = d; kmin = k; }
    }
    float* num = g_num + (size_t)(rbase + kmin)*EMBED;
    #pragma unroll
    for (int t = 0; t < 12; t++) atomicAdd(num + lane + t*32, xv[t]);
    if (lane == 0) atomicAdd(&g_den[rbase + kmin], 1.f);
}

__global__ void k_update() {
    int r = blockIdx.x;
    int c = threadIdx.x;   // 384
    float den = g_den[r];
    float cv = g_cent[(size_t)r*EMBED + c];
    if (den > 0.f) cv = g_num[(size_t)r*EMBED + c] / fmaxf(den, 1e-6f);
    g_cent[(size_t)r*EMBED + c] = cv;
    g_num[(size_t)r*EMBED + c] = 0.f;
    if (c == 0) g_den[r] = 0.f;
    __shared__ float red[384];
    red[c] = cv*cv; __syncthreads();
    if (c < 128) red[c] += red[c+128] + red[c+256];
    __syncthreads();
    for (int o = 64; o; o >>= 1) { if (c < o) red[c] += red[c+o]; __syncthreads(); }
    if (c == 0) g_csq[r] = red[0];
}

// ---------------- GEMM  C[M,N] = epi(A[M,K] (+A2) (*rowscale) @ B[K,N] + bias (+res)) ----------------
#define GBM 128
#define GBN 64
#define GBK 16
__global__ __launch_bounds__(256) void k_gemm(
    const float* __restrict__ A, const float* __restrict__ A2, const float* __restrict__ rowscale,
    const float* __restrict__ Bw, const float* __restrict__ bias, const float* __restrict__ res,
    float* __restrict__ C, int N, int K, int relu)
{
    __shared__ float As[GBK][GBM];
    __shared__ float Bs[GBK][GBN];
    int tid = threadIdx.x;
    int bm = blockIdx.y * GBM;
    int bn = blockIdx.x * GBN;
    int arow = tid >> 2;          // 0..63
    int acol = (tid & 3) * 4;     // 0,4,8,12
    int brow = tid >> 4;          // 0..15
    int bcol = (tid & 15) * 4;    // 0..60
    int trow = (tid >> 4) * 8;    // 0..120
    int tcol = (tid & 15) * 4;    // 0..60
    float acc[8][4];
    #pragma unroll
    for (int i = 0; i < 8; i++)
        #pragma unroll
        for (int j = 0; j < 4; j++) acc[i][j] = 0.f;

    for (int k0 = 0; k0 < K; k0 += GBK) {
        #pragma unroll
        for (int h = 0; h < 2; h++) {
            int r = arow + h*64;
            size_t gi = (size_t)(bm + r)*K + k0 + acol;
            float4 va = *(const float4*)(A + gi);
            if (A2) {
                float4 v2 = *(const float4*)(A2 + gi);
                va.x += v2.x; va.y += v2.y; va.z += v2.z; va.w += v2.w;
            }
            if (rowscale) {
                float s = rowscale[bm + r];
                va.x *= s; va.y *= s; va.z *= s; va.w *= s;
            }
            As[acol+0][r] = va.x; As[acol+1][r] = va.y;
            As[acol+2][r] = va.z; As[acol+3][r] = va.w;
        }
        {
            size_t gb = (size_t)(k0 + brow)*N + bn + bcol;
            if (bn + GBN <= N) {
                float4 vb = *(const float4*)(Bw + gb);
                Bs[brow][bcol] = vb.x; Bs[brow][bcol+1] = vb.y;
                Bs[brow][bcol+2] = vb.z; Bs[brow][bcol+3] = vb.w;
            } else {
                #pragma unroll
                for (int j = 0; j < 4; j++)
                    Bs[brow][bcol+j] = (bn + bcol + j < N) ? Bw[gb + j] : 0.f;
            }
        }
        __syncthreads();
        #pragma unroll
        for (int kk = 0; kk < GBK; kk++) {
            float af[8], bf[4];
            #pragma unroll
            for (int i = 0; i < 8; i++) af[i] = As[kk][trow + i];
            #pragma unroll
            for (int j = 0; j < 4; j++) bf[j] = Bs[kk][tcol + j];
            #pragma unroll
            for (int i = 0; i < 8; i++)
                #pragma unroll
                for (int j = 0; j < 4; j++) acc[i][j] += af[i]*bf[j];
        }
        __syncthreads();
    }
    #pragma unroll
    for (int i = 0; i < 8; i++) {
        int row = bm + trow + i;
        #pragma unroll
        for (int j = 0; j < 4; j++) {
            int col = bn + tcol + j;
            if (col < N) {
                float v = acc[i][j];
                if (bias) v += bias[col];
                if (res)  v += res[(size_t)row*N + col];
                if (relu) v = fmaxf(v, 0.f);
                C[(size_t)row*N + col] = v;
            }
        }
    }
}

// ---------------- softmax over 9 points ----------------
__global__ void k_softmax() {
    int t = blockIdx.x * blockDim.x + threadIdx.x;
    if (t >= BNTOT*NHEADS) return;
    float* a = g_aw + (size_t)t*NPOINTS;
    float m = a[0];
    #pragma unroll
    for (int p = 1; p < NPOINTS; p++) m = fmaxf(m, a[p]);
    float e[NPOINTS]; float s = 0.f;
    #pragma unroll
    for (int p = 0; p < NPOINTS; p++) { e[p] = expf(a[p] - m); s += e[p]; }
    #pragma unroll
    for (int p = 0; p < NPOINTS; p++) a[p] = e[p] / s;
}

// ---------------- deformable bilinear sample + point-weighted sum ----------------
__global__ void k_sample() {
    int gw = (blockIdx.x * blockDim.x + threadIdx.x) >> 5;
    int lane = threadIdx.x & 31;
    if (gw >= BNTOT*NHEADS) return;
    int h = gw % NHEADS;
    int bn = gw / NHEADS;
    int n = bn % NN, b = bn / NN;
    int i = n / WW, j = n % WW;
    const float* vbase = g_v + (size_t)b*NN*EMBED + h*32;
    const float* offp  = g_off + ((size_t)bn*NHEADS + h)*NPOINTS*2;
    const float* awp   = g_aw  + ((size_t)bn*NHEADS + h)*NPOINTS;
    float refx = ((float)j + 0.5f) / (float)WW;
    float refy = ((float)i + 0.5f) / (float)HH;
    float acc = 0.f;
    #pragma unroll
    for (int p = 0; p < NPOINTS; p++) {
        float ox = offp[2*p], oy = offp[2*p+1];
        float locx = refx + ox * (1.f/(float)WW);
        float locy = refy + oy * (1.f/(float)HH);
        float xf = locx * (float)WW - 0.5f;
        float yf = locy * (float)HH - 0.5f;
        float x0 = floorf(xf), y0 = floorf(yf);
        float wx = xf - x0, wy = yf - y0;
        int ix = (int)x0, iy = (int)y0;
        float v00 = 0.f, v01 = 0.f, v10 = 0.f, v11 = 0.f;
        bool xa = (ix >= 0 && ix < WW), xb = (ix+1 >= 0 && ix+1 < WW);
        bool ya = (iy >= 0 && iy < HH), yb = (iy+1 >= 0 && iy+1 < HH);
        if (xa && ya) v00 = vbase[(size_t)(iy*WW + ix)*EMBED + lane];
        if (xb && ya) v01 = vbase[(size_t)(iy*WW + ix + 1)*EMBED + lane];
        if (xa && yb) v10 = vbase[(size_t)((iy+1)*WW + ix)*EMBED + lane];
        if (xb && yb) v11 = vbase[(size_t)((iy+1)*WW + ix + 1)*EMBED + lane];
        float out = v00*(1.f-wx)*(1.f-wy) + v01*wx*(1.f-wy)
                  + v10*(1.f-wx)*wy      + v11*wx*wy;
        acc += awp[p] * out;
    }
    g_attn[(size_t)bn*EMBED + h*32 + lane] = acc;
}

// ---------------- layernorm ----------------
__global__ void k_ln(const float* __restrict__ in, const float* __restrict__ g,
                     const float* __restrict__ b, float* __restrict__ out) {
    int row = blockIdx.x;
    int tid = threadIdx.x;   // 128
    const float* xr = in + (size_t)row*EMBED;
    float v0 = xr[tid], v1 = xr[tid+128], v2 = xr[tid+256];
    __shared__ float red[128];
    red[tid] = v0 + v1 + v2; __syncthreads();
    for (int o = 64; o; o >>= 1) { if (tid < o) red[tid] += red[tid+o]; __syncthreads(); }
    float m = red[0] / (float)EMBED;
    __syncthreads();
    float d0 = v0 - m, d1 = v1 - m, d2 = v2 - m;
    red[tid] = d0*d0 + d1*d1 + d2*d2; __syncthreads();
    for (int o = 64; o; o >>= 1) { if (tid < o) red[tid] += red[tid+o]; __syncthreads(); }
    float var = red[0] / (float)EMBED;
    float r = rsqrtf(var + 1e-5f);
    float* orow = out + (size_t)row*EMBED;
    orow[tid]     = d0*r*g[tid]     + b[tid];
    orow[tid+128] = d1*r*g[tid+128] + b[tid+128];
    orow[tid+256] = d2*r*g[tid+256] + b[tid+256];
}

// ---------------- output concat ----------------
__global__ void k_output(float* __restrict__ out) {
    int t = blockIdx.x * blockDim.x + threadIdx.x;
    const int ROWS = NN + KTOT;
    if (t >= BB*ROWS*EMBED) return;
    int c = t % EMBED;
    int r = (t / EMBED) % ROWS;
    int b = t / (EMBED*ROWS);
    float v;
    if (r < NN) v = g_x[((size_t)b*NN + r)*EMBED + c];
    else        v = g_cent[((size_t)b*KTOT + (r - NN))*EMBED + c];
    out[t] = v;
}

// ---------------- host launcher ----------------
extern "C" void kernel_launch(void* const* d_in, const int* in_sizes, int n_in,
                              void* d_out, int out_size) {
    const float* s_x  = (const float*)d_in[0];
    const float* pad  = (const float*)d_in[1];
    const float* supp = (const float*)d_in[2];
    const float* Wv   = (const float*)d_in[3];
    const float* bv   = (const float*)d_in[4];
    const float* Woff = (const float*)d_in[5];
    const float* boff = (const float*)d_in[6];
    const float* Wa   = (const float*)d_in[7];
    const float* ba   = (const float*)d_in[8];
    const float* Wout = (const float*)d_in[9];
    const float* bout = (const float*)d_in[10];
    const float* ln1g = (const float*)d_in[11];
    const float* ln1b = (const float*)d_in[12];
    const float* Wf1  = (const float*)d_in[13];
    const float* Wf2  = (const float*)d_in[14];
    const float* ln2g = (const float*)d_in[15];
    const float* ln2b = (const float*)d_in[16];
    float* out = (float*)d_out;

    static float *p_x=nullptr, *p_pos, *p_tmp, *p_v, *p_attn, *p_off, *p_aw, *p_hid, *p_notpad;
    if (!p_x) {
        cudaGetSymbolAddress((void**)&p_x, g_x);
        cudaGetSymbolAddress((void**)&p_pos, g_pos);
        cudaGetSymbolAddress((void**)&p_tmp, g_tmp);
        cudaGetSymbolAddress((void**)&p_v, g_v);
        cudaGetSymbolAddress((void**)&p_attn, g_attn);
        cudaGetSymbolAddress((void**)&p_off, g_off);
        cudaGetSymbolAddress((void**)&p_aw, g_aw);
        cudaGetSymbolAddress((void**)&p_hid, g_hid);
        cudaGetSymbolAddress((void**)&p_notpad, g_notpad);
    }

    // prep
    k_masks<<<(BB*KTOT*EMBED + 255)/256, 256>>>(pad, supp);
    k_transpose<<<dim3(NN/32, EMBED/32, BB), dim3(32,8)>>>(s_x);
    k_xsq<<<BNTOT, 128>>>();
    k_cumx<<<1, 256>>>();
    k_cumy<<<1, 256>>>();
    k_pos<<<BNTOT, EMBED>>>();

    // k-means (on initial x)
    k_compact<<<BB*2, 256>>>();
    k_csq<<<BB*KTOT, 128>>>();
    for (int it = 0; it < NITER; it++) {
        k_assign<<<dim3(NN/8, BB*2), 256>>>();
        k_update<<<BB*KTOT, EMBED>>>();
    }

    // transformer layers
    for (int l = 0; l < NLAYERS; l++) {
        const float* wv  = Wv   + (size_t)l*EMBED*EMBED;
        const float* bvl = bv   + (size_t)l*EMBED;
        const float* wo  = Woff + (size_t)l*EMBED*(NHEADS*NPOINTS*2);
        const float* bol = boff + (size_t)l*(NHEADS*NPOINTS*2);
        const float* wa  = Wa   + (size_t)l*EMBED*(NHEADS*NPOINTS);
        const float* bal = ba   + (size_t)l*(NHEADS*NPOINTS);
        const float* wu  = Wout + (size_t)l*EMBED*EMBED;
        const float* bul = bout + (size_t)l*EMBED;
        const float* w1  = Wf1  + (size_t)l*EMBED*FFN;
        const float* w2  = Wf2  + (size_t)l*FFN*EMBED;

        // v = (x * notpad) @ Wv + bv
        k_gemm<<<dim3(EMBED/GBN, BNTOT/GBM), 256>>>(p_x, nullptr, p_notpad, wv, bvl, nullptr, p_v, EMBED, EMBED, 0);
        // off = (x+pos) @ Woff + boff    [N=216]
        k_gemm<<<dim3((216+GBN-1)/GBN, BNTOT/GBM), 256>>>(p_x, p_pos, nullptr, wo, bol, nullptr, p_off, 216, EMBED, 0);
        // aw  = (x+pos) @ Wa + ba        [N=108]
        k_gemm<<<dim3((108+GBN-1)/GBN, BNTOT/GBM), 256>>>(p_x, p_pos, nullptr, wa, bal, nullptr, p_aw, 108, EMBED, 0);
        k_softmax<<<(BNTOT*NHEADS + 255)/256, 256>>>();
        k_sample<<<(BNTOT*NHEADS)/8, 256>>>();
        // tmp = x + attn @ Wout + bout
        k_gemm<<<dim3(EMBED/GBN, BNTOT/GBM), 256>>>(p_attn, nullptr, nullptr, wu, bul, p_x, p_tmp, EMBED, EMBED, 0);
        k_ln<<<BNTOT, 128>>>(p_tmp, ln1g + l*EMBED, ln1b + l*EMBED, p_x);
        // hid = relu(x @ Wf1)
        k_gemm<<<dim3(FFN/GBN, BNTOT/GBM), 256>>>(p_x, nullptr, nullptr, w1, nullptr, nullptr, p_hid, FFN, EMBED, 1);
        // tmp = x + hid @ Wf2
        k_gemm<<<dim3(EMBED/GBN, BNTOT/GBM), 256>>>(p_hid, nullptr, nullptr, w2, nullptr, p_x, p_tmp, EMBED, FFN, 0);
        k_ln<<<BNTOT, 128>>>(p_tmp, ln2g + l*EMBED, ln2b + l*EMBED, p_x);
    }

    // concat [x, fg_c, bg_c]
    k_output<<<(BB*(NN+KTOT)*EMBED + 255)/256, 256>>>(out);
}

// round 3
// speedup vs baseline: 1.4723x; 1.4723x over previous
#include <cuda_runtime.h>
#include <math.h>

#define EMBED 384
#define NHEADS 12
#define NPOINTS 9
#define NLAYERS 2
#define KFG 20
#define KBG 50
#define KTOT 70
#define NITER 10
#define BB 4
#define HH 64
#define WW 64
#define NN (HH*WW)
#define BNTOT (BB*NN)
#define FFN 1152

// ---------------- scratch (device globals; allocation-free) ----------------
__device__ float g_x[BNTOT*EMBED];
__device__ float g_pos[BNTOT*EMBED];
__device__ float g_tmp[BNTOT*EMBED];
__device__ float g_v[BNTOT*EMBED];
__device__ float g_attn[BNTOT*EMBED];
__device__ float g_off[BNTOT*NHEADS*NPOINTS*2];
__device__ float g_aw[BNTOT*NHEADS*NPOINTS];
__device__ float g_hid[BNTOT*FFN];
__device__ float g_notpad[BNTOT];
__device__ float g_wfg[BNTOT];
__device__ float g_wbg[BNTOT];
__device__ float g_xsq[BNTOT];
__device__ float g_xemb[BNTOT];
__device__ float g_yemb[BNTOT];
__device__ int   g_list[BB*2*NN];
__device__ int   g_cnt[BB*2];
__device__ float g_cent[BB*KTOT*EMBED];
__device__ float g_num[BB*KTOT*EMBED];
__device__ float g_den[BB*KTOT];
__device__ float g_csq[BB*KTOT];

// ---------------- prep ----------------
__global__ void k_masks(const float* __restrict__ pad, const float* __restrict__ supp) {
    int i = blockIdx.x * blockDim.x + threadIdx.x;
    if (i < BNTOT) {
        float np = (pad[i] == 255.0f) ? 0.f : 1.f;
        float ob = (supp[i] == 1.0f) ? 1.f : 0.f;
        g_notpad[i] = np;
        g_wfg[i] = ob * np;
        g_wbg[i] = (1.f - ob) * np;
    }
    if (i < BB*KTOT*EMBED) g_num[i] = 0.f;
    if (i < BB*KTOT) g_den[i] = 0.f;
}

__global__ void k_transpose(const float* __restrict__ sx) {
    __shared__ float tile[32][33];
    int b = blockIdx.z;
    int n0 = blockIdx.x * 32, c0 = blockIdx.y * 32;
    for (int r = threadIdx.y; r < 32; r += 8)
        tile[r][threadIdx.x] = sx[((size_t)b*EMBED + c0 + r)*NN + n0 + threadIdx.x];
    __syncthreads();
    for (int r = threadIdx.y; r < 32; r += 8)
        g_x[((size_t)b*NN + n0 + r)*EMBED + c0 + threadIdx.x] = tile[threadIdx.x][r];
}

__global__ void k_xsq() {
    int row = blockIdx.x;
    const float* xr = g_x + (size_t)row*EMBED;
    int tid = threadIdx.x;
    float s = 0.f;
    for (int c = tid; c < EMBED; c += 128) { float v = xr[c]; s += v*v; }
    __shared__ float red[128];
    red[tid] = s; __syncthreads();
    for (int o = 64; o; o >>= 1) { if (tid < o) red[tid] += red[tid+o]; __syncthreads(); }
    if (tid == 0) g_xsq[row] = red[0];
}

// cumulative-sum positional embeddings (x rows + y cols in one kernel)
__global__ void k_cum() {
    int t = blockIdx.x * blockDim.x + threadIdx.x;
    const float sc = 6.283185307179586f;
    if (t < BB*HH) {
        int b = t / HH, i = t % HH;
        const float* np_ = g_notpad + (b*NN + i*WW);
        float tot = 0.f;
        for (int j = 0; j < WW; j++) tot += np_[j];
        float mul = sc / (tot + 1e-6f);
        float cum = 0.f;
        for (int j = 0; j < WW; j++) {
            cum += np_[j];
            g_xemb[b*NN + i*WW + j] = cum * mul;
        }
    } else if (t < BB*HH + BB*WW) {
        int t2 = t - BB*HH;
        int b = t2 / WW, j = t2 % WW;
        const float* np_ = g_notpad + b*NN + j;
        float tot = 0.f;
        for (int i = 0; i < HH; i++) tot += np_[i*WW];
        float mul = sc / (tot + 1e-6f);
        float cum = 0.f;
        for (int i = 0; i < HH; i++) {
            cum += np_[i*WW];
            g_yemb[b*NN + i*WW + j] = cum * mul;
        }
    }
}

__global__ void k_pos() {
    int idx = blockIdx.x;          // b*NN + n
    int c = threadIdx.x;           // 0..383
    float emb; int cc;
    if (c < 192) { emb = g_yemb[idx]; cc = c; }
    else         { emb = g_xemb[idx]; cc = c - 192; }
    float e = (float)(2*(cc/2)) / 192.f;
    float inv = exp2f(-e * 13.287712379549449f);
    float s = emb * inv;
    float v = (cc & 1) ? cosf(s) : sinf(s);
    g_pos[(size_t)idx*EMBED + c] = v;
}

// ---------------- k-means ----------------
__global__ void k_compact() {
    int b = blockIdx.x >> 1, grp = blockIdx.x & 1;
    const float* w = (grp == 0 ? g_wfg : g_wbg) + b*NN;
    int* list = g_list + (b*2 + grp)*NN;
    __shared__ int sscan[256];
    __shared__ int sbase;
    int tid = threadIdx.x;
    if (tid == 0) sbase = 0;
    __syncthreads();
    for (int pass = 0; pass < 2; pass++) {
        for (int c0 = 0; c0 < NN; c0 += 256) {
            int n = c0 + tid;
            int f = (pass == 0) ? (w[n] > 0.f ? 1 : 0) : (w[n] > 0.f ? 0 : 1);
            sscan[tid] = f; __syncthreads();
            for (int o = 1; o < 256; o <<= 1) {
                int v = (tid >= o) ? sscan[tid-o] : 0;
                __syncthreads();
                sscan[tid] += v;
                __syncthreads();
            }
            int mybase = sbase;
            if (f) list[mybase + sscan[tid] - 1] = n;
            __syncthreads();
            if (tid == 255) sbase = mybase + sscan[255];
            __syncthreads();
        }
        if (pass == 0 && tid == 0) g_cnt[b*2 + grp] = sbase;
        __syncthreads();
    }
    int K = (grp == 0) ? KFG : KBG;
    float* cent = g_cent + (size_t)(b*KTOT + (grp ? KFG : 0))*EMBED;
    for (int t = tid; t < K*EMBED; t += 256) {
        int k = t / EMBED, c = t % EMBED;
        cent[(size_t)k*EMBED + c] = g_x[((size_t)b*NN + list[k])*EMBED + c];
    }
}

__global__ void k_csq() {
    int r = blockIdx.x;
    int tid = threadIdx.x;
    const float* cr = g_cent + (size_t)r*EMBED;
    float s = 0.f;
    for (int c = tid; c < EMBED; c += 128) { float v = cr[c]; s += v*v; }
    __shared__ float red[128];
    red[tid] = s; __syncthreads();
    for (int o = 64; o; o >>= 1) { if (tid < o) red[tid] += red[tid+o]; __syncthreads(); }
    if (tid == 0) g_csq[r] = red[0];
}

__global__ void k_assign() {
    int bg = blockIdx.y;
    int b = bg >> 1, grp = bg & 1;
    int warp = threadIdx.x >> 5, lane = threadIdx.x & 31;
    int pi = blockIdx.x * (blockDim.x >> 5) + warp;
    int cnt = g_cnt[bg];
    if (pi >= cnt) return;
    int n = g_list[bg*NN + pi];
    int K = grp ? KBG : KFG;
    int rbase = b*KTOT + (grp ? KFG : 0);
    const float* xr = g_x + ((size_t)b*NN + n)*EMBED;
    float xv[12];
    #pragma unroll
    for (int t = 0; t < 12; t++) xv[t] = xr[lane + t*32];
    float xsq = g_xsq[b*NN + n];
    float dmin = INFINITY; int kmin = 0;
    for (int k = 0; k < K; k++) {
        const float* cr = g_cent + (size_t)(rbase + k)*EMBED;
        float p = 0.f;
        #pragma unroll
        for (int t = 0; t < 12; t++) p += xv[t]*cr[lane + t*32];
        #pragma unroll
        for (int o = 16; o; o >>= 1) p += __shfl_xor_sync(0xFFFFFFFFu, p, o);
        float d = (xsq - 2.f*p) + g_csq[rbase + k];
        if (d < dmin) { dmin = d; kmin = k; }
    }
    float* num = g_num + (size_t)(rbase + kmin)*EMBED;
    #pragma unroll
    for (int t = 0; t < 12; t++) atomicAdd(num + lane + t*32, xv[t]);
    if (lane == 0) atomicAdd(&g_den[rbase + kmin], 1.f);
}

__global__ void k_update() {
    int r = blockIdx.x;
    int c = threadIdx.x;   // 384
    float den = g_den[r];
    float cv = g_cent[(size_t)r*EMBED + c];
    if (den > 0.f) cv = g_num[(size_t)r*EMBED + c] / fmaxf(den, 1e-6f);
    g_cent[(size_t)r*EMBED + c] = cv;
    g_num[(size_t)r*EMBED + c] = 0.f;
    if (c == 0) g_den[r] = 0.f;
    __shared__ float red[384];
    red[c] = cv*cv; __syncthreads();
    if (c < 128) red[c] += red[c+128] + red[c+256];
    __syncthreads();
    for (int o = 64; o; o >>= 1) { if (c < o) red[c] += red[c+o]; __syncthreads(); }
    if (c == 0) g_csq[r] = red[0];
}

// ---------------- TF32 tensor-core GEMM ----------------
// C[M,N] = epi( (A (+A2)) (*rowscale) @ B[K,N] + bias (+res) ), tf32 inputs fp32 accum
#define TM 128
#define TN 128
#define TK 32
#define ASTR (TM+8)
#define BSTR (TN+8)

__device__ __forceinline__ float tf32r(float x) {
    asm("cvt.rna.tf32.f32 %0, %1;" : "=f"(x) : "f"(x));
    return x;
}

__global__ __launch_bounds__(256) void k_gemm_tc(
    const float* __restrict__ A, const float* __restrict__ A2, const float* __restrict__ rowscale,
    const float* __restrict__ Bw, const float* __restrict__ bias, const float* __restrict__ res,
    float* __restrict__ C, int N, int K, int relu)
{
    __shared__ float As[TK*ASTR];
    __shared__ float Bs[TK*BSTR];
    int tid = threadIdx.x;
    int lane = tid & 31, warp = tid >> 5;
    int wm = warp & 1, wn = warp >> 1;   // warps: 2 (M) x 4 (N); warp tile 64x32
    int bm = blockIdx.y * TM, bn = blockIdx.x * TN;
    int ar = lane >> 2, ac = lane & 3;   // fragment row/col within group

    float acc[4][4][4];
    #pragma unroll
    for (int i = 0; i < 4; i++)
        #pragma unroll
        for (int j = 0; j < 4; j++)
            #pragma unroll
            for (int q = 0; q < 4; q++) acc[i][j][q] = 0.f;

    int arow = tid >> 2;            // 0..63
    int akc  = (tid & 3) * 4;       // 0,4,8,12
    int bkr  = tid >> 3;            // 0..31
    int bnc  = (tid & 7) * 16;      // 0..112

    for (int k0 = 0; k0 < K; k0 += TK) {
        // A tile -> As[k][m] (transposed store), fused A2-add / rowscale / tf32 round
        #pragma unroll
        for (int h2 = 0; h2 < 2; h2++) {
            int r = arow + h2*64;
            float s = rowscale ? rowscale[bm + r] : 1.f;
            #pragma unroll
            for (int hk = 0; hk < 2; hk++) {
                int kk = akc + hk*16;
                size_t gi = (size_t)(bm + r)*K + k0 + kk;
                float4 v = *(const float4*)(A + gi);
                if (A2) {
                    float4 v2 = *(const float4*)(A2 + gi);
                    v.x += v2.x; v.y += v2.y; v.z += v2.z; v.w += v2.w;
                }
                if (rowscale) { v.x *= s; v.y *= s; v.z *= s; v.w *= s; }
                As[(kk+0)*ASTR + r] = tf32r(v.x);
                As[(kk+1)*ASTR + r] = tf32r(v.y);
                As[(kk+2)*ASTR + r] = tf32r(v.z);
                As[(kk+3)*ASTR + r] = tf32r(v.w);
            }
        }
        // B tile -> Bs[k][n]
        #pragma unroll
        for (int h = 0; h < 4; h++) {
            int nc = bnc + h*4;
            int gcol = bn + nc;
            float4 v;
            if (gcol + 3 < N) {
                v = *(const float4*)(Bw + (size_t)(k0 + bkr)*N + gcol);
            } else {
                const float* bp = Bw + (size_t)(k0 + bkr)*N;
                v.x = (gcol+0 < N) ? bp[gcol+0] : 0.f;
                v.y = (gcol+1 < N) ? bp[gcol+1] : 0.f;
                v.z = (gcol+2 < N) ? bp[gcol+2] : 0.f;
                v.w = (gcol+3 < N) ? bp[gcol+3] : 0.f;
            }
            v.x = tf32r(v.x); v.y = tf32r(v.y); v.z = tf32r(v.z); v.w = tf32r(v.w);
            *(float4*)&Bs[bkr*BSTR + nc] = v;
        }
        __syncthreads();
        #pragma unroll
        for (int ks = 0; ks < 4; ks++) {
            int kb = ks*8;
            unsigned a[4][4], b[4][2];
            #pragma unroll
            for (int i = 0; i < 4; i++) {
                int m = wm*64 + i*16;
                a[i][0] = __float_as_uint(As[(kb+ac)*ASTR   + m + ar]);
                a[i][1] = __float_as_uint(As[(kb+ac)*ASTR   + m + ar + 8]);
                a[i][2] = __float_as_uint(As[(kb+ac+4)*ASTR + m + ar]);
                a[i][3] = __float_as_uint(As[(kb+ac+4)*ASTR + m + ar + 8]);
            }
            #pragma unroll
            for (int j = 0; j < 4; j++) {
                int n = wn*32 + j*8 + ar;
                b[j][0] = __float_as_uint(Bs[(kb+ac)*BSTR   + n]);
                b[j][1] = __float_as_uint(Bs[(kb+ac+4)*BSTR + n]);
            }
            #pragma unroll
            for (int i = 0; i < 4; i++)
                #pragma unroll
                for (int j = 0; j < 4; j++)
                    asm volatile(
                        "mma.sync.aligned.m16n8k8.row.col.f32.tf32.tf32.f32 "
                        "{%0,%1,%2,%3}, {%4,%5,%6,%7}, {%8,%9}, {%0,%1,%2,%3};"
                        : "+f"(acc[i][j][0]), "+f"(acc[i][j][1]),
                          "+f"(acc[i][j][2]), "+f"(acc[i][j][3])
                        : "r"(a[i][0]), "r"(a[i][1]), "r"(a[i][2]), "r"(a[i][3]),
                          "r"(b[j][0]), "r"(b[j][1]));
        }
        __syncthreads();
    }
    // epilogue
    #pragma unroll
    for (int i = 0; i < 4; i++) {
        int row = bm + wm*64 + i*16 + ar;
        #pragma unroll
        for (int j = 0; j < 4; j++) {
            int col = bn + wn*32 + j*8 + ac*2;
            #pragma unroll
            for (int h = 0; h < 2; h++) {
                int rr = row + h*8;
                float v0 = acc[i][j][2*h], v1 = acc[i][j][2*h+1];
                if (col < N) {
                    if (bias) v0 += bias[col];
                    if (res)  v0 += res[(size_t)rr*N + col];
                    if (relu) v0 = fmaxf(v0, 0.f);
                    C[(size_t)rr*N + col] = v0;
                }
                if (col + 1 < N) {
                    if (bias) v1 += bias[col+1];
                    if (res)  v1 += res[(size_t)rr*N + col + 1];
                    if (relu) v1 = fmaxf(v1, 0.f);
                    C[(size_t)rr*N + col + 1] = v1;
                }
            }
        }
    }
}

// ---------------- deformable bilinear sample + softmax + point-weighted sum ----------------
__global__ void k_sample() {
    int gw = (blockIdx.x * blockDim.x + threadIdx.x) >> 5;
    int lane = threadIdx.x & 31;
    if (gw >= BNTOT*NHEADS) return;
    int h = gw % NHEADS;
    int bn = gw / NHEADS;
    int n = bn % NN, b = bn / NN;
    int i = n / WW, j = n % WW;
    const float* vbase = g_v + (size_t)b*NN*EMBED + h*32;
    const float* offp  = g_off + ((size_t)bn*NHEADS + h)*NPOINTS*2;
    const float* awp   = g_aw  + ((size_t)bn*NHEADS + h)*NPOINTS;

    // warp softmax over 9 raw scores
    float raw = (lane < NPOINTS) ? awp[lane] : -INFINITY;
    float m = raw;
    #pragma unroll
    for (int o = 16; o; o >>= 1) m = fmaxf(m, __shfl_xor_sync(0xFFFFFFFFu, m, o));
    float e = (lane < NPOINTS) ? expf(raw - m) : 0.f;
    float s = e;
    #pragma unroll
    for (int o = 16; o; o >>= 1) s += __shfl_xor_sync(0xFFFFFFFFu, s, o);
    float sinv = 1.f / s;

    float refx = ((float)j + 0.5f) / (float)WW;
    float refy = ((float)i + 0.5f) / (float)HH;
    float acc = 0.f;
    #pragma unroll
    for (int p = 0; p < NPOINTS; p++) {
        float w = __shfl_sync(0xFFFFFFFFu, e, p) * sinv;
        float ox = offp[2*p], oy = offp[2*p+1];
        float locx = refx + ox * (1.f/(float)WW);
        float locy = refy + oy * (1.f/(float)HH);
        float xf = locx * (float)WW - 0.5f;
        float yf = locy * (float)HH - 0.5f;
        float x0 = floorf(xf), y0 = floorf(yf);
        float wx = xf - x0, wy = yf - y0;
        int ix = (int)x0, iy = (int)y0;
        float v00 = 0.f, v01 = 0.f, v10 = 0.f, v11 = 0.f;
        bool xa = (ix >= 0 && ix < WW), xb = (ix+1 >= 0 && ix+1 < WW);
        bool ya = (iy >= 0 && iy < HH), yb = (iy+1 >= 0 && iy+1 < HH);
        if (xa && ya) v00 = vbase[(size_t)(iy*WW + ix)*EMBED + lane];
        if (xb && ya) v01 = vbase[(size_t)(iy*WW + ix + 1)*EMBED + lane];
        if (xa && yb) v10 = vbase[(size_t)((iy+1)*WW + ix)*EMBED + lane];
        if (xb && yb) v11 = vbase[(size_t)((iy+1)*WW + ix + 1)*EMBED + lane];
        float out = v00*(1.f-wx)*(1.f-wy) + v01*wx*(1.f-wy)
                  + v10*(1.f-wx)*wy      + v11*wx*wy;
        acc += w * out;
    }
    g_attn[(size_t)bn*EMBED + h*32 + lane] = acc;
}

// ---------------- layernorm ----------------
__global__ void k_ln(const float* __restrict__ in, const float* __restrict__ g,
                     const float* __restrict__ b, float* __restrict__ out) {
    int row = blockIdx.x;
    int tid = threadIdx.x;   // 128
    const float* xr = in + (size_t)row*EMBED;
    float v0 = xr[tid], v1 = xr[tid+128], v2 = xr[tid+256];
    __shared__ float red[128];
    red[tid] = v0 + v1 + v2; __syncthreads();
    for (int o = 64; o; o >>= 1) { if (tid < o) red[tid] += red[tid+o]; __syncthreads(); }
    float m = red[0] / (float)EMBED;
    __syncthreads();
    float d0 = v0 - m, d1 = v1 - m, d2 = v2 - m;
    red[tid] = d0*d0 + d1*d1 + d2*d2; __syncthreads();
    for (int o = 64; o; o >>= 1) { if (tid < o) red[tid] += red[tid+o]; __syncthreads(); }
    float var = red[0] / (float)EMBED;
    float r = rsqrtf(var + 1e-5f);
    float* orow = out + (size_t)row*EMBED;
    orow[tid]     = d0*r*g[tid]     + b[tid];
    orow[tid+128] = d1*r*g[tid+128] + b[tid+128];
    orow[tid+256] = d2*r*g[tid+256] + b[tid+256];
}

// ---------------- output concat ----------------
__global__ void k_output(float* __restrict__ out) {
    int t = blockIdx.x * blockDim.x + threadIdx.x;
    const int ROWS = NN + KTOT;
    if (t >= BB*ROWS*EMBED) return;
    int c = t % EMBED;
    int r = (t / EMBED) % ROWS;
    int b = t / (EMBED*ROWS);
    float v;
    if (r < NN) v = g_x[((size_t)b*NN + r)*EMBED + c];
    else        v = g_cent[((size_t)b*KTOT + (r - NN))*EMBED + c];
    out[t] = v;
}

// ---------------- host launcher ----------------
extern "C" void kernel_launch(void* const* d_in, const int* in_sizes, int n_in,
                              void* d_out, int out_size) {
    const float* s_x  = (const float*)d_in[0];
    const float* pad  = (const float*)d_in[1];
    const float* supp = (const float*)d_in[2];
    const float* Wv   = (const float*)d_in[3];
    const float* bv   = (const float*)d_in[4];
    const float* Woff = (const float*)d_in[5];
    const float* boff = (const float*)d_in[6];
    const float* Wa   = (const float*)d_in[7];
    const float* ba   = (const float*)d_in[8];
    const float* Wout = (const float*)d_in[9];
    const float* bout = (const float*)d_in[10];
    const float* ln1g = (const float*)d_in[11];
    const float* ln1b = (const float*)d_in[12];
    const float* Wf1  = (const float*)d_in[13];
    const float* Wf2  = (const float*)d_in[14];
    const float* ln2g = (const float*)d_in[15];
    const float* ln2b = (const float*)d_in[16];
    float* out = (float*)d_out;

    static float *p_x=nullptr, *p_pos, *p_tmp, *p_v, *p_attn, *p_off, *p_aw, *p_hid, *p_notpad;
    if (!p_x) {
        cudaGetSymbolAddress((void**)&p_x, g_x);
        cudaGetSymbolAddress((void**)&p_pos, g_pos);
        cudaGetSymbolAddress((void**)&p_tmp, g_tmp);
        cudaGetSymbolAddress((void**)&p_v, g_v);
        cudaGetSymbolAddress((void**)&p_attn, g_attn);
        cudaGetSymbolAddress((void**)&p_off, g_off);
        cudaGetSymbolAddress((void**)&p_aw, g_aw);
        cudaGetSymbolAddress((void**)&p_hid, g_hid);
        cudaGetSymbolAddress((void**)&p_notpad, g_notpad);
    }

    // prep
    k_masks<<<(BB*KTOT*EMBED + 255)/256, 256>>>(pad, supp);
    k_transpose<<<dim3(NN/32, EMBED/32, BB), dim3(32,8)>>>(s_x);
    k_xsq<<<BNTOT, 128>>>();
    k_cum<<<2, 256>>>();
    k_pos<<<BNTOT, EMBED>>>();

    // k-means (on initial x)
    k_compact<<<BB*2, 256>>>();
    k_csq<<<BB*KTOT, 128>>>();
    for (int it = 0; it < NITER; it++) {
        k_assign<<<dim3(NN/8, BB*2), 256>>>();
        k_update<<<BB*KTOT, EMBED>>>();
    }

    // transformer layers
    for (int l = 0; l < NLAYERS; l++) {
        const float* wv  = Wv   + (size_t)l*EMBED*EMBED;
        const float* bvl = bv   + (size_t)l*EMBED;
        const float* wo  = Woff + (size_t)l*EMBED*(NHEADS*NPOINTS*2);
        const float* bol = boff + (size_t)l*(NHEADS*NPOINTS*2);
        const float* wa  = Wa   + (size_t)l*EMBED*(NHEADS*NPOINTS);
        const float* bal = ba   + (size_t)l*(NHEADS*NPOINTS);
        const float* wu  = Wout + (size_t)l*EMBED*EMBED;
        const float* bul = bout + (size_t)l*EMBED;
        const float* w1  = Wf1  + (size_t)l*EMBED*FFN;
        const float* w2  = Wf2  + (size_t)l*FFN*EMBED;

        // v = (x * notpad) @ Wv + bv
        k_gemm_tc<<<dim3(EMBED/TN, BNTOT/TM), 256>>>(p_x, nullptr, p_notpad, wv, bvl, nullptr, p_v, EMBED, EMBED, 0);
        // off = (x+pos) @ Woff + boff  [N=216]
        k_gemm_tc<<<dim3((216+TN-1)/TN, BNTOT/TM), 256>>>(p_x, p_pos, nullptr, wo, bol, nullptr, p_off, 216, EMBED, 0);
        // aw  = (x+pos) @ Wa + ba      [N=108]  (raw scores; softmax fused into k_sample)
        k_gemm_tc<<<dim3((108+TN-1)/TN, BNTOT/TM), 256>>>(p_x, p_pos, nullptr, wa, bal, nullptr, p_aw, 108, EMBED, 0);
        k_sample<<<(BNTOT*NHEADS)/8, 256>>>();
        // tmp = x + attn @ Wout + bout
        k_gemm_tc<<<dim3(EMBED/TN, BNTOT/TM), 256>>>(p_attn, nullptr, nullptr, wu, bul, p_x, p_tmp, EMBED, EMBED, 0);
        k_ln<<<BNTOT, 128>>>(p_tmp, ln1g + l*EMBED, ln1b + l*EMBED, p_x);
        // hid = relu(x @ Wf1)
        k_gemm_tc<<<dim3(FFN/TN, BNTOT/TM), 256>>>(p_x, nullptr, nullptr, w1, nullptr, nullptr, p_hid, FFN, EMBED, 1);
        // tmp = x + hid @ Wf2
        k_gemm_tc<<<dim3(EMBED/TN, BNTOT/TM), 256>>>(p_hid, nullptr, nullptr, w2, nullptr, p_x, p_tmp, EMBED, FFN, 0);
        k_ln<<<BNTOT, 128>>>(p_tmp, ln2g + l*EMBED, ln2b + l*EMBED, p_x);
    }

    // concat [x, fg_c, bg_c]
    k_output<<<(BB*(NN+KTOT)*EMBED + 255)/256, 256>>>(out);
}